// round 2
// baseline (speedup 1.0000x reference)
#include <cuda_runtime.h>
#include <cstdint>

// ============================================================
// out[8192,4096] = x @ W^T + b + 2*((x @ A^T) @ B^T)
// Folded: Weff = W + 2*(B@A);  out = Xr @ Weff^T + b
// GEMM via warp-level mma.sync m16n8k8 tf32 (sm_103 family target:
// tcgen05 is sm_103a-only and the harness targets plain sm_103).
// Operands RN-rounded to tf32 to avoid truncation bias.
// ============================================================

#define M_DIM 8192
#define N_DIM 4096
#define K_DIM 4096

#define BM 128
#define BN 256
#define BK 32
#define STAGES 4
#define NK (K_DIM / BK)        // 128

// padded smem rows: 32 tf32 + 4 pad = 36 words = 144B (16B multiple)
#define PAD_K 36
#define A_STAGE_W (BM * PAD_K)             // 4608 words
#define B_STAGE_W (BN * PAD_K)             // 9216 words
#define STAGE_W   (A_STAGE_W + B_STAGE_W)  // 13824 words = 55296 B
#define SMEM_TOTAL (STAGES * STAGE_W * 4)  // 221184 B

// scratch (static device globals — no runtime allocation)
__device__ __align__(16) float g_Weff[(size_t)N_DIM * K_DIM];
__device__ __align__(16) float g_Xr[(size_t)M_DIM * K_DIM];

// ---------------- PTX helpers ----------------
__device__ __forceinline__ uint32_t smem_u32(const void* p) {
    uint32_t a;
    asm("{ .reg .u64 t; cvta.to.shared.u64 t, %1; cvt.u32.u64 %0, t; }" : "=r"(a) : "l"(p));
    return a;
}

#define CP_ASYNC16(dst, src) \
    asm volatile("cp.async.cg.shared.global [%0], [%1], 16;" :: "r"(dst), "l"(src) : "memory")
#define CP_COMMIT() asm volatile("cp.async.commit_group;" ::: "memory")
#define CP_WAIT(n)  asm volatile("cp.async.wait_group %0;" :: "n"(n) : "memory")

__device__ __forceinline__ void mma_tf32(float c[4], const uint32_t a[4], const uint32_t b[2]) {
    asm volatile(
        "mma.sync.aligned.m16n8k8.row.col.f32.tf32.tf32.f32 "
        "{%0,%1,%2,%3}, {%4,%5,%6,%7}, {%8,%9}, {%0,%1,%2,%3};\n"
        : "+f"(c[0]), "+f"(c[1]), "+f"(c[2]), "+f"(c[3])
        : "r"(a[0]), "r"(a[1]), "r"(a[2]), "r"(a[3]), "r"(b[0]), "r"(b[1]));
}

// ---------------- prep kernels ----------------

// RN-round x to tf32 (hardware tf32 conversion truncates; RN keeps it unbiased)
__global__ __launch_bounds__(256) void roundx_kernel(const float4* __restrict__ x) {
    size_t i = (size_t)blockIdx.x * 256 + threadIdx.x;
    float4 v = x[i];
    uint32_t a, b, c, d;
    asm("cvt.rna.tf32.f32 %0, %1;" : "=r"(a) : "f"(v.x));
    asm("cvt.rna.tf32.f32 %0, %1;" : "=r"(b) : "f"(v.y));
    asm("cvt.rna.tf32.f32 %0, %1;" : "=r"(c) : "f"(v.z));
    asm("cvt.rna.tf32.f32 %0, %1;" : "=r"(d) : "f"(v.w));
    float4 o;
    o.x = __uint_as_float(a); o.y = __uint_as_float(b);
    o.z = __uint_as_float(c); o.w = __uint_as_float(d);
    reinterpret_cast<float4*>(g_Xr)[i] = o;
}

// Weff[o,i] = round_tf32( W[o,i] + 2 * sum_r B[o,r] * A[r,i] )
__global__ __launch_bounds__(256) void weff_kernel(const float* __restrict__ W,
                                                   const float* __restrict__ A,
                                                   const float* __restrict__ B) {
    __shared__ float As[16][256];
    int t = threadIdx.x;
    int i0 = blockIdx.x * 256;
    int o0 = blockIdx.y * 64;
#pragma unroll
    for (int r = 0; r < 16; r++)
        As[r][t] = A[r * 4096 + i0 + t];
    __syncthreads();
    for (int oo = 0; oo < 64; oo++) {
        int o = o0 + oo;
        const float* Br = B + o * 16;
        float s = 0.f;
#pragma unroll
        for (int r = 0; r < 16; r++) s += Br[r] * As[r][t];
        float v = W[((size_t)o << 12) + i0 + t] + 2.0f * s;
        uint32_t t32;
        asm("cvt.rna.tf32.f32 %0, %1;" : "=r"(t32) : "f"(v));
        g_Weff[((size_t)o << 12) + i0 + t] = __uint_as_float(t32);
    }
}

// ---------------- main GEMM: mma.sync tf32 ----------------
// CTA 128x256x32, 8 warps in 2(M)x4(N), warp tile 64x64.
// 4-stage cp.async pipeline. Accumulate in registers, direct STG epilogue.
__global__ __launch_bounds__(256, 1)
void lora_gemm_kernel(const float* __restrict__ bias, float* __restrict__ out) {
    extern __shared__ float smem[];
    uint32_t smem_base = smem_u32(smem);

    int tid = threadIdx.x;
    int wid = tid >> 5;
    int lane = tid & 31;
    int warp_m = (wid & 1) * 64;        // 0 or 64
    int warp_n = (wid >> 1) * 64;       // 0,64,128,192

    int m0 = blockIdx.y * BM;
    int n0 = blockIdx.x * BN;

    const float* gA = g_Xr + ((size_t)m0 << 12);
    const float* gB = g_Weff + ((size_t)n0 << 12);

    // cp.async one stage (BK columns of A[128] and B[256], 16B chunks, padded rows)
    auto load_stage = [&](int stage, int kt) {
        uint32_t sA = smem_base + (uint32_t)(stage * STAGE_W * 4);
        uint32_t sB = sA + A_STAGE_W * 4;
        int kbase = kt << 5;   // kt*32
#pragma unroll
        for (int i = 0; i < 4; i++) {        // A: 128 rows * 8 chunks = 1024
            int ch = tid + i * 256;
            int row = ch >> 3, c = ch & 7;
            CP_ASYNC16(sA + (uint32_t)(row * PAD_K + c * 4) * 4,
                       gA + (((size_t)row) << 12) + kbase + (c << 2));
        }
#pragma unroll
        for (int i = 0; i < 8; i++) {        // B: 256 rows * 8 chunks = 2048
            int ch = tid + i * 256;
            int row = ch >> 3, c = ch & 7;
            CP_ASYNC16(sB + (uint32_t)(row * PAD_K + c * 4) * 4,
                       gB + (((size_t)row) << 12) + kbase + (c << 2));
        }
        CP_COMMIT();
    };

    float acc[4][8][4];
#pragma unroll
    for (int mt = 0; mt < 4; mt++)
#pragma unroll
        for (int nt = 0; nt < 8; nt++)
#pragma unroll
            for (int i = 0; i < 4; i++) acc[mt][nt][i] = 0.f;

    // prologue: fill stages 0..2
    load_stage(0, 0);
    load_stage(1, 1);
    load_stage(2, 2);

    int lr = lane >> 2;     // 0..7
    int lc = lane & 3;      // 0..3

    for (int k = 0; k < NK; k++) {
        if (k < NK - 2)       CP_WAIT(2);
        else if (k == NK - 2) CP_WAIT(1);
        else                  CP_WAIT(0);
        __syncthreads();

        // prefetch stage k+3 into slot (k+3)&3 (that slot was consumed at iter k-1)
        if (k + 3 < NK) load_stage((k + 3) & 3, k + 3);

        const float* As = smem + (size_t)(k & 3) * STAGE_W + warp_m * PAD_K;
        const float* Bs = smem + (size_t)(k & 3) * STAGE_W + A_STAGE_W + warp_n * PAD_K;

#pragma unroll
        for (int ks = 0; ks < 4; ks++) {
            int kk = ks * 8;
            uint32_t af[4][4];
            uint32_t bf[8][2];
#pragma unroll
            for (int mt = 0; mt < 4; mt++) {
                const float* p = As + (mt * 16 + lr) * PAD_K + kk + lc;
                af[mt][0] = __float_as_uint(p[0]);
                af[mt][1] = __float_as_uint(p[8 * PAD_K]);
                af[mt][2] = __float_as_uint(p[4]);
                af[mt][3] = __float_as_uint(p[8 * PAD_K + 4]);
            }
#pragma unroll
            for (int nt = 0; nt < 8; nt++) {
                const float* p = Bs + (nt * 8 + lr) * PAD_K + kk + lc;
                bf[nt][0] = __float_as_uint(p[0]);
                bf[nt][1] = __float_as_uint(p[4]);
            }
#pragma unroll
            for (int mt = 0; mt < 4; mt++)
#pragma unroll
                for (int nt = 0; nt < 8; nt++)
                    mma_tf32(acc[mt][nt], af[mt], bf[nt]);
        }
        __syncthreads();
    }

    // epilogue: direct stores + bias. c0,c1 -> (row, 2*lc+{0,1}); c2,c3 -> row+8.
#pragma unroll
    for (int nt = 0; nt < 8; nt++) {
        int col = n0 + warp_n + nt * 8 + 2 * lc;
        float bv0 = bias[col];
        float bv1 = bias[col + 1];
#pragma unroll
        for (int mt = 0; mt < 4; mt++) {
            int row = m0 + warp_m + mt * 16 + lr;
            float2 v0 = make_float2(acc[mt][nt][0] + bv0, acc[mt][nt][1] + bv1);
            float2 v1 = make_float2(acc[mt][nt][2] + bv0, acc[mt][nt][3] + bv1);
            *reinterpret_cast<float2*>(out + (((size_t)row) << 12) + col) = v0;
            *reinterpret_cast<float2*>(out + (((size_t)(row + 8)) << 12) + col) = v1;
        }
    }
}

// ---------------- launch ----------------
extern "C" void kernel_launch(void* const* d_in, const int* in_sizes, int n_in,
                              void* d_out, int out_size) {
    const float* x = (const float*)d_in[0];   // [8192, 4096]
    const float* W = (const float*)d_in[1];   // [4096, 4096]
    const float* b = (const float*)d_in[2];   // [4096]
    const float* A = (const float*)d_in[3];   // [16, 4096]
    const float* B = (const float*)d_in[4];   // [4096, 16]
    float* out = (float*)d_out;               // [8192, 4096]

    cudaFuncSetAttribute(lora_gemm_kernel,
                         cudaFuncAttributeMaxDynamicSharedMemorySize, SMEM_TOTAL);

    // 1) RN-round x -> tf32 scratch
    roundx_kernel<<<(M_DIM * (size_t)K_DIM) / 4 / 256, 256>>>(
        reinterpret_cast<const float4*>(x));
    // 2) Weff = round_tf32(W + 2*B@A)
    weff_kernel<<<dim3(16, 64), 256>>>(W, A, B);
    // 3) out = Xr @ Weff^T + b   (mma.sync tf32)
    lora_gemm_kernel<<<dim3(N_DIM / BN, M_DIM / BM), 256, SMEM_TOTAL>>>(b, out);
}

// round 7
// speedup vs baseline: 1.0329x; 1.0329x over previous
#include <cuda_runtime.h>
#include <cstdint>

// ============================================================
// out[8192,4096] = x @ W^T + b + 2*((x @ A^T) @ B^T)
// Folded: Weff = W + 2*(B@A);  out = Xr @ Weff^T + b
// GEMM via warp-level mma.sync m16n8k8 tf32, operands RN-rounded.
// R4 == R3 resubmit (infra failure): single-barrier multistage
// mainloop, uniform cp.async groups, fragment double-buffering.
// ============================================================

#define M_DIM 8192
#define N_DIM 4096
#define K_DIM 4096

#define BM 128
#define BN 256
#define BK 32
#define STAGES 4
#define NK (K_DIM / BK)        // 128

// padded smem rows: 32 tf32 + 4 pad = 36 words = 144B (16B multiple)
#define PAD_K 36
#define A_STAGE_W (BM * PAD_K)             // 4608 words
#define B_STAGE_W (BN * PAD_K)             // 9216 words
#define STAGE_W   (A_STAGE_W + B_STAGE_W)  // 13824 words = 55296 B
#define SMEM_TOTAL (STAGES * STAGE_W * 4)  // 221184 B

// scratch (static device globals — no runtime allocation)
__device__ __align__(16) float g_Weff[(size_t)N_DIM * K_DIM];
__device__ __align__(16) float g_Xr[(size_t)M_DIM * K_DIM];

// ---------------- PTX helpers ----------------
__device__ __forceinline__ uint32_t smem_u32(const void* p) {
    uint32_t a;
    asm("{ .reg .u64 t; cvta.to.shared.u64 t, %1; cvt.u32.u64 %0, t; }" : "=r"(a) : "l"(p));
    return a;
}

#define CP_ASYNC16(dst, src) \
    asm volatile("cp.async.cg.shared.global [%0], [%1], 16;" :: "r"(dst), "l"(src) : "memory")
#define CP_COMMIT() asm volatile("cp.async.commit_group;" ::: "memory")
#define CP_WAIT(n)  asm volatile("cp.async.wait_group %0;" :: "n"(n) : "memory")

__device__ __forceinline__ void mma_tf32(float c[4], const uint32_t a[4], const uint32_t b[2]) {
    asm volatile(
        "mma.sync.aligned.m16n8k8.row.col.f32.tf32.tf32.f32 "
        "{%0,%1,%2,%3}, {%4,%5,%6,%7}, {%8,%9}, {%0,%1,%2,%3};\n"
        : "+f"(c[0]), "+f"(c[1]), "+f"(c[2]), "+f"(c[3])
        : "r"(a[0]), "r"(a[1]), "r"(a[2]), "r"(a[3]), "r"(b[0]), "r"(b[1]));
}

// ---------------- prep kernels ----------------

// RN-round x to tf32 (hardware tf32 path truncates; RN keeps it unbiased)
__global__ __launch_bounds__(256) void roundx_kernel(const float4* __restrict__ x) {
    size_t i = (size_t)blockIdx.x * 256 + threadIdx.x;
    float4 v = x[i];
    uint32_t a, b, c, d;
    asm("cvt.rna.tf32.f32 %0, %1;" : "=r"(a) : "f"(v.x));
    asm("cvt.rna.tf32.f32 %0, %1;" : "=r"(b) : "f"(v.y));
    asm("cvt.rna.tf32.f32 %0, %1;" : "=r"(c) : "f"(v.z));
    asm("cvt.rna.tf32.f32 %0, %1;" : "=r"(d) : "f"(v.w));
    float4 o;
    o.x = __uint_as_float(a); o.y = __uint_as_float(b);
    o.z = __uint_as_float(c); o.w = __uint_as_float(d);
    reinterpret_cast<float4*>(g_Xr)[i] = o;
}

// Weff[o,i] = round_tf32( W[o,i] + 2 * sum_r B[o,r] * A[r,i] )
__global__ __launch_bounds__(256) void weff_kernel(const float* __restrict__ W,
                                                   const float* __restrict__ A,
                                                   const float* __restrict__ B) {
    __shared__ float As[16][256];
    int t = threadIdx.x;
    int i0 = blockIdx.x * 256;
    int o0 = blockIdx.y * 64;
#pragma unroll
    for (int r = 0; r < 16; r++)
        As[r][t] = A[r * 4096 + i0 + t];
    __syncthreads();
    for (int oo = 0; oo < 64; oo++) {
        int o = o0 + oo;
        const float* Br = B + o * 16;
        float s = 0.f;
#pragma unroll
        for (int r = 0; r < 16; r++) s += Br[r] * As[r][t];
        float v = W[((size_t)o << 12) + i0 + t] + 2.0f * s;
        uint32_t t32;
        asm("cvt.rna.tf32.f32 %0, %1;" : "=r"(t32) : "f"(v));
        g_Weff[((size_t)o << 12) + i0 + t] = __uint_as_float(t32);
    }
}

// ---------------- main GEMM: mma.sync tf32 ----------------
// CTA 128x256x32, 8 warps in 2(M)x4(N), warp tile 64x64.
// 4-stage cp.async pipeline, ONE __syncthreads per K-iteration.
__global__ __launch_bounds__(256, 1)
void lora_gemm_kernel(const float* __restrict__ bias, float* __restrict__ out) {
    extern __shared__ float smem[];
    uint32_t smem_base = smem_u32(smem);

    int tid = threadIdx.x;
    int wid = tid >> 5;
    int lane = tid & 31;
    int warp_m = (wid & 1) * 64;        // 0 or 64
    int warp_n = (wid >> 1) * 64;       // 0,64,128,192

    int m0 = blockIdx.y * BM;
    int n0 = blockIdx.x * BN;

    const float* gA = g_Xr + ((size_t)m0 << 12);
    const float* gB = g_Weff + ((size_t)n0 << 12);

    // cp.async one stage (BK cols of A[128] and B[256], 16B chunks, padded rows)
    auto load_stage = [&](int stage, int kt) {
        uint32_t sA = smem_base + (uint32_t)(stage * STAGE_W * 4);
        uint32_t sB = sA + A_STAGE_W * 4;
        int kbase = kt << 5;   // kt*32
#pragma unroll
        for (int i = 0; i < 4; i++) {        // A: 128 rows * 8 chunks = 1024
            int ch = tid + i * 256;
            int row = ch >> 3, c = ch & 7;
            CP_ASYNC16(sA + (uint32_t)(row * PAD_K + c * 4) * 4,
                       gA + (((size_t)row) << 12) + kbase + (c << 2));
        }
#pragma unroll
        for (int i = 0; i < 8; i++) {        // B: 256 rows * 8 chunks = 2048
            int ch = tid + i * 256;
            int row = ch >> 3, c = ch & 7;
            CP_ASYNC16(sB + (uint32_t)(row * PAD_K + c * 4) * 4,
                       gB + (((size_t)row) << 12) + kbase + (c << 2));
        }
        CP_COMMIT();
    };

    float acc[4][8][4];
#pragma unroll
    for (int mt = 0; mt < 4; mt++)
#pragma unroll
        for (int nt = 0; nt < 8; nt++)
#pragma unroll
            for (int i = 0; i < 4; i++) acc[mt][nt][i] = 0.f;

    // prologue: fill stages 0..2 (3 groups in flight)
    load_stage(0, 0);
    load_stage(1, 1);
    load_stage(2, 2);

    int lr = lane >> 2;     // 0..7
    int lc = lane & 3;      // 0..3

    const uint32_t a_off = (uint32_t)(warp_m + lr) * PAD_K + lc;   // + mt*16*PAD_K + ks*8
    const uint32_t b_off = (uint32_t)(warp_n + lr) * PAD_K + lc;   // + nt*8*PAD_K  + ks*8

    uint32_t afr[2][4][4];
    uint32_t bfr[2][8][2];

#pragma unroll 4
    for (int k = 0; k < NK; k++) {
        // exactly 3 groups outstanding at this point -> wait tile k
        CP_WAIT(2);
        __syncthreads();

        // prefetch tile k+3 into slot (k+3)&3 == (k-1)&3 (consumed at iter k-1;
        // top barrier above guarantees every warp is past it). Always commit a
        // group so the outstanding-group count stays uniform.
        if (k + 3 < NK) load_stage((k + 3) & 3, k + 3);
        else            CP_COMMIT();

        const float* As = smem + (size_t)(k & 3) * STAGE_W + a_off;
        const float* Bs = smem + (size_t)(k & 3) * STAGE_W + A_STAGE_W + b_off;

        // load fragments for ks=0
#pragma unroll
        for (int mt = 0; mt < 4; mt++) {
            const float* p = As + mt * 16 * PAD_K;
            afr[0][mt][0] = __float_as_uint(p[0]);
            afr[0][mt][1] = __float_as_uint(p[8 * PAD_K]);
            afr[0][mt][2] = __float_as_uint(p[4]);
            afr[0][mt][3] = __float_as_uint(p[8 * PAD_K + 4]);
        }
#pragma unroll
        for (int nt = 0; nt < 8; nt++) {
            const float* p = Bs + nt * 8 * PAD_K;
            bfr[0][nt][0] = __float_as_uint(p[0]);
            bfr[0][nt][1] = __float_as_uint(p[4]);
        }

#pragma unroll
        for (int ks = 0; ks < 4; ks++) {
            int cur = ks & 1, nxt = cur ^ 1;
            if (ks < 3) {   // prefetch fragments for ks+1
                int kk = (ks + 1) * 8;
#pragma unroll
                for (int mt = 0; mt < 4; mt++) {
                    const float* p = As + mt * 16 * PAD_K + kk;
                    afr[nxt][mt][0] = __float_as_uint(p[0]);
                    afr[nxt][mt][1] = __float_as_uint(p[8 * PAD_K]);
                    afr[nxt][mt][2] = __float_as_uint(p[4]);
                    afr[nxt][mt][3] = __float_as_uint(p[8 * PAD_K + 4]);
                }
#pragma unroll
                for (int nt = 0; nt < 8; nt++) {
                    const float* p = Bs + nt * 8 * PAD_K + kk;
                    bfr[nxt][nt][0] = __float_as_uint(p[0]);
                    bfr[nxt][nt][1] = __float_as_uint(p[4]);
                }
            }
#pragma unroll
            for (int mt = 0; mt < 4; mt++)
#pragma unroll
                for (int nt = 0; nt < 8; nt++)
                    mma_tf32(acc[mt][nt], afr[cur][mt], bfr[cur][nt]);
        }
        // NOTE: no trailing barrier — next iteration's top barrier covers the
        // write-after-read hazard on the recycled stage.
    }

    // epilogue: direct stores + bias. c0,c1 -> (row, 2*lc+{0,1}); c2,c3 -> row+8.
#pragma unroll
    for (int nt = 0; nt < 8; nt++) {
        int col = n0 + warp_n + nt * 8 + 2 * lc;
        float bv0 = bias[col];
        float bv1 = bias[col + 1];
#pragma unroll
        for (int mt = 0; mt < 4; mt++) {
            int row = m0 + warp_m + mt * 16 + lr;
            float2 v0 = make_float2(acc[mt][nt][0] + bv0, acc[mt][nt][1] + bv1);
            float2 v1 = make_float2(acc[mt][nt][2] + bv0, acc[mt][nt][3] + bv1);
            *reinterpret_cast<float2*>(out + (((size_t)row) << 12) + col) = v0;
            *reinterpret_cast<float2*>(out + (((size_t)(row + 8)) << 12) + col) = v1;
        }
    }
}

// ---------------- launch ----------------
extern "C" void kernel_launch(void* const* d_in, const int* in_sizes, int n_in,
                              void* d_out, int out_size) {
    const float* x = (const float*)d_in[0];   // [8192, 4096]
    const float* W = (const float*)d_in[1];   // [4096, 4096]
    const float* b = (const float*)d_in[2];   // [4096]
    const float* A = (const float*)d_in[3];   // [16, 4096]
    const float* B = (const float*)d_in[4];   // [4096, 16]
    float* out = (float*)d_out;               // [8192, 4096]

    cudaFuncSetAttribute(lora_gemm_kernel,
                         cudaFuncAttributeMaxDynamicSharedMemorySize, SMEM_TOTAL);

    // 1) RN-round x -> tf32 scratch
    roundx_kernel<<<(M_DIM * (size_t)K_DIM) / 4 / 256, 256>>>(
        reinterpret_cast<const float4*>(x));
    // 2) Weff = round_tf32(W + 2*B@A)
    weff_kernel<<<dim3(16, 64), 256>>>(W, A, B);
    // 3) out = Xr @ Weff^T + b   (mma.sync tf32)
    lora_gemm_kernel<<<dim3(N_DIM / BN, M_DIM / BM), 256, SMEM_TOTAL>>>(b, out);
}